// round 4
// baseline (speedup 1.0000x reference)
#include <cuda_runtime.h>

// Problem constants (fixed shapes for this problem)
#define NNODE 10000
#define NEDGE 160000
#define NMUL  16

// Scratch (static device arrays — cudaMalloc is forbidden)
__device__ __align__(16) float g_T[756];                 // T[b][a*9+d], b-major, stride 84
__device__ __align__(16) float g_w[(size_t)NEDGE * 48];  // MLP output w[e][48]

typedef unsigned long long u64;

// ---------------------------------------------------------------------------
// packed f32x2 helpers (Blackwell FFMA2)
// ---------------------------------------------------------------------------
__device__ __forceinline__ u64 pk2(float x, float y) {
    u64 r; asm("mov.b64 %0, {%1, %2};" : "=l"(r) : "f"(x), "f"(y)); return r;
}
__device__ __forceinline__ void up2(u64 v, float& x, float& y) {
    asm("mov.b64 {%0, %1}, %2;" : "=f"(x), "=f"(y) : "l"(v));
}
__device__ __forceinline__ u64 ffma2(u64 a, u64 b, u64 c) {
    u64 d; asm("fma.rn.f32x2 %0, %1, %2, %3;" : "=l"(d) : "l"(a), "l"(b), "l"(c));
    return d;
}

// ---------------------------------------------------------------------------
// ShiftedSoftPlus: softplus(x) - ln2, stable form max(x,0)+log1p(exp(-|x|))
// ---------------------------------------------------------------------------
__device__ __forceinline__ float sspf(float x) {
    float e = __expf(-fabsf(x));
    return fmaxf(x, 0.0f) + __logf(1.0f + e) - 0.69314718055994531f;
}

// ---------------------------------------------------------------------------
// kprep: build T[b][a*9+d] = sum_{s,t} Gx[a,s,t] * Gf[b,s,t] * P[s,t,d] / denom
// ---------------------------------------------------------------------------
__device__ __forceinline__ float gridval(const float* __restrict__ Ur,
                                         const float* __restrict__ Ui,
                                         int a, int s, int t,
                                         const float* C, const float* S) {
    float acc = 0.0f;
    #pragma unroll
    for (int v = 0; v < 5; v++) {
        float gr = 0.0f, gi = 0.0f;
        int jj = (v + 4) % 9 - 2;                 // padded col -> U col
        if (jj >= 0 && jj < 5) {
            #pragma unroll
            for (int u = 0; u < 9; u++) {
                int ii = (u + 4) % 9 - 2;         // padded row -> U row
                if (ii >= 0 && ii < 5) {
                    float cr = Ur[a * 25 + ii * 5 + jj];
                    float ci = Ui[a * 25 + ii * 5 + jj];
                    int k = (u * s) % 9;
                    gr += cr * C[k] - ci * S[k];
                    gi += cr * S[k] + ci * C[k];
                }
            }
        }
        if (v == 0) {
            acc += gr;                             // Im(DC) dropped (numpy irfft)
        } else {
            int k2 = (v * t) % 9;
            acc += 2.0f * (gr * C[k2] - gi * S[k2]);
        }
    }
    return acc * (1.0f / 81.0f);
}

__global__ void kprep(const float* __restrict__ Uxr, const float* __restrict__ Uxi,
                      const float* __restrict__ Ufr, const float* __restrict__ Ufi,
                      const float* __restrict__ Vr,  const float* __restrict__ Vi,
                      const float* __restrict__ denom) {
    __shared__ float C9[9], S9[9];
    __shared__ float Gx[729], Gf[729], Pm[729];
    int tid = threadIdx.x;

    if (tid < 9) {
        double ang = 2.0 * 3.14159265358979323846 * (double)tid / 9.0;
        C9[tid] = (float)cos(ang);
        S9[tid] = (float)sin(ang);
    }
    __syncthreads();

    if (tid < 729) {
        {   // grid bases: tid = a*81 + s*9 + t
            int a = tid / 81, s = (tid / 9) % 9, t = tid % 9;
            Gx[tid] = gridval(Uxr, Uxi, a, s, t, C9, S9);
            Gf[tid] = gridval(Ufr, Ufi, a, s, t, C9, S9);
        }
        {   // projection: tid = (s*9+t)*9 + d
            int st = tid / 9, d = tid % 9;
            int s = st / 9, t = st % 9;
            float p = 0.0f;
            #pragma unroll
            for (int u = 0; u < 9; u++) {
                #pragma unroll
                for (int k = 0; k < 5; k++) {
                    int th = (u * s + k * t) % 9;
                    p += Vr[u * 45 + k * 9 + d] * C9[th]
                       + Vi[u * 45 + k * 9 + d] * S9[th];
                }
            }
            Pm[tid] = p;
        }
    }
    __syncthreads();

    float inv = 1.0f / denom[0];
    if (tid < 729) {
        int a = tid / 81, b = (tid / 9) % 9, d = tid % 9;
        float acc = 0.0f;
        #pragma unroll 9
        for (int st = 0; st < 81; st++)
            acc += Gx[a * 81 + st] * Gf[b * 81 + st] * Pm[st * 9 + d];
        g_T[b * 84 + a * 9 + d] = acc * inv;     // b-major layout for kmsg
    }
}

// ---------------------------------------------------------------------------
// kzero: clear output (harness poisons it with 0xAA)
// ---------------------------------------------------------------------------
__global__ void kzero(float4* __restrict__ o, int n4) {
    int i = blockIdx.x * 256 + threadIdx.x;
    if (i < n4) o[i] = make_float4(0.f, 0.f, 0.f, 0.f);
}

// ---------------------------------------------------------------------------
// kmlp: per-edge 3-layer MLP (8 -> 64 -> 64 -> 48), all layers j-outer with
// packed FFMA2: hoisted broadcast pk2 (one per input activation) and 32
// independent accumulator chains (full FMA-pipe throughput).
// ---------------------------------------------------------------------------
__global__ void __launch_bounds__(128) kmlp(const float* __restrict__ win,
                                            const float* __restrict__ W1,
                                            const float* __restrict__ W2,
                                            const float* __restrict__ W3,
                                            int E) {
    __shared__ float4 w1s[128];   // 8x64
    __shared__ float4 w2s[1024];  // 64x64
    __shared__ float4 w3s[768];   // 64x48
    int tid = threadIdx.x;

    const float4* W1v = (const float4*)W1;
    const float4* W2v = (const float4*)W2;
    const float4* W3v = (const float4*)W3;
    w1s[tid] = W1v[tid];
    #pragma unroll
    for (int i = 0; i < 8; i++) w2s[tid + i * 128] = W2v[tid + i * 128];
    #pragma unroll
    for (int i = 0; i < 6; i++) w3s[tid + i * 128] = W3v[tid + i * 128];
    __syncthreads();

    int e = blockIdx.x * 128 + tid;
    if (e >= E) return;

    const ulonglong2* w1p = (const ulonglong2*)w1s;
    const ulonglong2* w2p = (const ulonglong2*)w2s;
    const ulonglong2* w3p = (const ulonglong2*)w3s;

    float4 wa = ((const float4*)win)[e * 2 + 0];
    float4 wb = ((const float4*)win)[e * 2 + 1];
    float wi[8] = {wa.x, wa.y, wa.z, wa.w, wb.x, wb.y, wb.z, wb.w};

    u64 acc[32];          // acc[t] holds outputs (2t, 2t+1)
    float h[64];

    // ----- layer 1: h = ssp((win @ W1) / sqrt(8)) -----
    #pragma unroll
    for (int t = 0; t < 32; t++) acc[t] = 0ull;
    #pragma unroll
    for (int i = 0; i < 8; i++) {
        u64 hi = pk2(wi[i], wi[i]);
        #pragma unroll
        for (int kq = 0; kq < 16; kq++) {
            ulonglong2 wp = w1p[i * 16 + kq];
            acc[2 * kq + 0] = ffma2(hi, wp.x, acc[2 * kq + 0]);
            acc[2 * kq + 1] = ffma2(hi, wp.y, acc[2 * kq + 1]);
        }
    }
    const float s1 = 0.35355339059327373f;
    #pragma unroll
    for (int t = 0; t < 32; t++) {
        float v0, v1; up2(acc[t], v0, v1);
        h[2 * t + 0] = sspf(v0 * s1);
        h[2 * t + 1] = sspf(v1 * s1);
    }

    // ----- layer 2: h = ssp((h @ W2) * 0.125) -----
    #pragma unroll
    for (int t = 0; t < 32; t++) acc[t] = 0ull;
    #pragma unroll 4
    for (int j = 0; j < 64; j++) {
        u64 hj = pk2(h[j], h[j]);
        #pragma unroll
        for (int kq = 0; kq < 16; kq++) {
            ulonglong2 wp = w2p[j * 16 + kq];
            acc[2 * kq + 0] = ffma2(hj, wp.x, acc[2 * kq + 0]);
            acc[2 * kq + 1] = ffma2(hj, wp.y, acc[2 * kq + 1]);
        }
    }
    #pragma unroll
    for (int t = 0; t < 32; t++) {
        float v0, v1; up2(acc[t], v0, v1);
        h[2 * t + 0] = sspf(v0 * 0.125f);
        h[2 * t + 1] = sspf(v1 * 0.125f);
    }

    // ----- layer 3: w = (h @ W3) * 0.125 -----
    u64 acc3[24];
    #pragma unroll
    for (int t = 0; t < 24; t++) acc3[t] = 0ull;
    #pragma unroll 4
    for (int j = 0; j < 64; j++) {
        u64 hj = pk2(h[j], h[j]);
        #pragma unroll
        for (int q = 0; q < 12; q++) {
            ulonglong2 wp = w3p[j * 12 + q];
            acc3[2 * q + 0] = ffma2(hj, wp.x, acc3[2 * q + 0]);
            acc3[2 * q + 1] = ffma2(hj, wp.y, acc3[2 * q + 1]);
        }
    }

    float4* gwv = (float4*)&g_w[(size_t)e * 48];
    #pragma unroll
    for (int q = 0; q < 12; q++) {
        float p0, p1, p2, p3;
        up2(acc3[2 * q + 0], p0, p1);
        up2(acc3[2 * q + 1], p2, p3);
        gwv[q] = make_float4(p0 * 0.125f, p1 * 0.125f, p2 * 0.125f, p3 * 0.125f);
    }
}

// ---------------------------------------------------------------------------
// kmsg: group-per-edge message + scatter.
//   Block = 252 threads = 7 groups of 36; each group owns one edge per round.
//   Stage: x[src] (36 coalesced float4), w[e] (12 float4), f9 into smem.
//   Sv[81] built cooperatively from b-major T (conflict-free LDS).
//   Each thread computes one aligned output float4 -> coalesced red.v4.
// ---------------------------------------------------------------------------
#define KMSG_R 16   // edge-rounds per block

__global__ void __launch_bounds__(252) kmsg(const float* __restrict__ x,
                                            const float* __restrict__ fsph,
                                            const int*   __restrict__ eidx,
                                            const float* __restrict__ aw,
                                            float* __restrict__ out,
                                            int E) {
    __shared__ __align__(16) float Tsh[756];
    __shared__ float awsh[27];
    __shared__ float f9s[7][9];
    __shared__ __align__(16) float Svsh[7][81];
    __shared__ __align__(16) float xsh[7][144];
    __shared__ __align__(16) float wsh[7][48];

    int tid = threadIdx.x;
    #pragma unroll
    for (int i = 0; i < 3; i++) Tsh[tid + i * 252] = g_T[tid + i * 252];
    if (tid < 27) awsh[tid] = aw[tid];

    int g = tid / 36;
    int r = tid - g * 36;
    int ebase = blockIdx.x * (7 * KMSG_R) + g;

    for (int round = 0; round < KMSG_R; round++) {
        __syncthreads();   // previous round's readers done; Tsh ready on round 0

        int e = ebase + round * 7;
        bool valid = (e < E);
        int dst = 0;

        if (valid) {
            dst = __ldg(&eidx[e]);
            int src = __ldg(&eidx[E + e]);
            if (r < 9) f9s[g][r] = __ldg(&fsph[(size_t)e * 9 + r]);
            float4 xv = __ldg(((const float4*)(x + (size_t)src * 144)) + r);
            ((float4*)xsh[g])[r] = xv;
            if (r < 12) {
                float4 wv = __ldg(((const float4*)(g_w + (size_t)e * 48)) + r);
                ((float4*)wsh[g])[r] = wv;
            }
        }
        __syncthreads();

        // Sv[a*9+d] = sum_b f9[b] * T[b][a*9+d]; thread r covers entries
        // r, r+36, and (r<9) r+72.
        {
            float fr[9];
            #pragma unroll
            for (int b = 0; b < 9; b++) fr[b] = f9s[g][b];
            float a1 = 0.f, a2 = 0.f, a3 = 0.f;
            #pragma unroll
            for (int b = 0; b < 9; b++) {
                float fb = fr[b];
                a1 += fb * Tsh[b * 84 + r];
                a2 += fb * Tsh[b * 84 + 36 + r];
                if (r < 9) a3 += fb * Tsh[b * 84 + 72 + r];
            }
            Svsh[g][r]      = a1;
            Svsh[g][36 + r] = a2;
            if (r < 9) Svsh[g][72 + r] = a3;
        }
        __syncthreads();

        if (valid) {
            float rr[4];
            #pragma unroll
            for (int i = 0; i < 4; i++) {
                int o = 4 * r + i;
                int m = o / 9;
                int d = o - 9 * m;
                float msg = 0.f;
                #pragma unroll
                for (int a = 0; a < 9; a++)
                    msg += xsh[g][m * 9 + a] * Svsh[g][a * 9 + d];
                float fac = wsh[g][3 * m + 0] * awsh[d]
                          + wsh[g][3 * m + 1] * awsh[9 + d]
                          + wsh[g][3 * m + 2] * awsh[18 + d];
                rr[i] = msg * fac;
            }
            float* ob = out + (size_t)dst * 144 + 4 * r;
            asm volatile("red.global.add.v4.f32 [%0], {%1, %2, %3, %4};"
                         :: "l"(ob), "f"(rr[0]), "f"(rr[1]), "f"(rr[2]), "f"(rr[3])
                         : "memory");
        }
    }
}

// ---------------------------------------------------------------------------
// kernel_launch
// inputs: 0:x 1:filter_sph 2:weight_in 3:edge_idx 4:Ux_re 5:Ux_im 6:Uf_re
//         7:Uf_im 8:Vout_re 9:Vout_im 10:W1 11:W2 12:W3 13:a_w 14:denominator
// ---------------------------------------------------------------------------
extern "C" void kernel_launch(void* const* d_in, const int* in_sizes, int n_in,
                              void* d_out, int out_size) {
    const float* x    = (const float*)d_in[0];
    const float* fsph = (const float*)d_in[1];
    const float* win  = (const float*)d_in[2];
    const int*   eidx = (const int*)  d_in[3];
    const float* Uxr  = (const float*)d_in[4];
    const float* Uxi  = (const float*)d_in[5];
    const float* Ufr  = (const float*)d_in[6];
    const float* Ufi  = (const float*)d_in[7];
    const float* Vr   = (const float*)d_in[8];
    const float* Vi   = (const float*)d_in[9];
    const float* W1   = (const float*)d_in[10];
    const float* W2   = (const float*)d_in[11];
    const float* W3   = (const float*)d_in[12];
    const float* aw   = (const float*)d_in[13];
    const float* den  = (const float*)d_in[14];
    float* out = (float*)d_out;

    int E = in_sizes[1] / 9;   // filter_sph is [E, 9]

    kprep<<<1, 729>>>(Uxr, Uxi, Ufr, Ufi, Vr, Vi, den);
    int n4 = out_size / 4;
    kzero<<<(n4 + 255) / 256, 256>>>((float4*)out, n4);
    kmlp<<<(E + 127) / 128, 128>>>(win, W1, W2, W3, E);
    int epb = 7 * KMSG_R;
    kmsg<<<(E + epb - 1) / epb, 252>>>(x, fsph, eidx, aw, out, E);
}

// round 5
// speedup vs baseline: 1.3216x; 1.3216x over previous
#include <cuda_runtime.h>

// Problem constants (fixed shapes for this problem)
#define NNODE 10000
#define NEDGE 160000
#define NMUL  16

// Scratch (static device arrays — cudaMalloc is forbidden)
__device__ __align__(16) float g_T[972];                 // T[(a*9+b)*12 + d], pad 12
__device__ __align__(16) float g_w[(size_t)NEDGE * 48];  // MLP output w[e][48]

typedef unsigned long long u64;

// ---------------------------------------------------------------------------
// packed f32x2 helpers (Blackwell FFMA2)
// ---------------------------------------------------------------------------
__device__ __forceinline__ u64 pk2(float x, float y) {
    u64 r; asm("mov.b64 %0, {%1, %2};" : "=l"(r) : "f"(x), "f"(y)); return r;
}
__device__ __forceinline__ void up2(u64 v, float& x, float& y) {
    asm("mov.b64 {%0, %1}, %2;" : "=f"(x), "=f"(y) : "l"(v));
}
__device__ __forceinline__ u64 ffma2(u64 a, u64 b, u64 c) {
    u64 d; asm("fma.rn.f32x2 %0, %1, %2, %3;" : "=l"(d) : "l"(a), "l"(b), "l"(c));
    return d;
}

__device__ __forceinline__ float sspf(float x) {
    float e = __expf(-fabsf(x));
    return fmaxf(x, 0.0f) + __logf(1.0f + e) - 0.69314718055994531f;
}

// ---------------------------------------------------------------------------
// gridval: real 9x9 grid value of one spherical basis vector through
// pad -> ifftshift -> truncate -> irfft2 (numpy Im(DC)-dropped convention)
// ---------------------------------------------------------------------------
__device__ __forceinline__ float gridval(const float* __restrict__ Ur,
                                         const float* __restrict__ Ui,
                                         int a, int s, int t,
                                         const float* C, const float* S) {
    float acc = 0.0f;
    #pragma unroll
    for (int v = 0; v < 5; v++) {
        float gr = 0.0f, gi = 0.0f;
        int jj = (v + 4) % 9 - 2;                 // padded col -> U col
        if (jj >= 0 && jj < 5) {
            #pragma unroll
            for (int u = 0; u < 9; u++) {
                int ii = (u + 4) % 9 - 2;         // padded row -> U row
                if (ii >= 0 && ii < 5) {
                    float cr = Ur[a * 25 + ii * 5 + jj];
                    float ci = Ui[a * 25 + ii * 5 + jj];
                    int k = (u * s) % 9;
                    gr += cr * C[k] - ci * S[k];
                    gi += cr * S[k] + ci * C[k];
                }
            }
        }
        if (v == 0) {
            acc += gr;                             // Im(DC) dropped
        } else {
            int k2 = (v * t) % 9;
            acc += 2.0f * (gr * C[k2] - gi * S[k2]);
        }
    }
    return acc * (1.0f / 81.0f);
}

// ---------------------------------------------------------------------------
// kpre: fused (a) zero out (all blocks, grid-stride), (b) kprep (block 0),
// (c) per-edge 3-layer MLP 8->64->64->48 in packed FFMA2 (all blocks).
// ---------------------------------------------------------------------------
__global__ void __launch_bounds__(128) kpre(
    const float* __restrict__ win,
    const float* __restrict__ W1,
    const float* __restrict__ W2,
    const float* __restrict__ W3,
    const float* __restrict__ Uxr, const float* __restrict__ Uxi,
    const float* __restrict__ Ufr, const float* __restrict__ Ufi,
    const float* __restrict__ Vr,  const float* __restrict__ Vi,
    const float* __restrict__ denom,
    float4* __restrict__ o4, int n4,
    int E) {
    __shared__ float4 w1s[128];   // 8x64
    __shared__ float4 w2s[1024];  // 64x64
    __shared__ float4 w3s[768];   // 64x48
    __shared__ float C9[9], S9[9];
    __shared__ float Gx[729], Gf[729], Pm[729];

    int tid = threadIdx.x;
    int bid = blockIdx.x;

    // ---- zero output (grid-stride) ----
    for (int i = bid * 128 + tid; i < n4; i += gridDim.x * 128)
        o4[i] = make_float4(0.f, 0.f, 0.f, 0.f);

    // ---- stage MLP weights ----
    const float4* W1v = (const float4*)W1;
    const float4* W2v = (const float4*)W2;
    const float4* W3v = (const float4*)W3;
    w1s[tid] = W1v[tid];
    #pragma unroll
    for (int i = 0; i < 8; i++) w2s[tid + i * 128] = W2v[tid + i * 128];
    #pragma unroll
    for (int i = 0; i < 6; i++) w3s[tid + i * 128] = W3v[tid + i * 128];

    // ---- kprep on block 0 only ----
    if (bid == 0) {
        if (tid < 9) {
            double ang = 2.0 * 3.14159265358979323846 * (double)tid / 9.0;
            C9[tid] = (float)cos(ang);
            S9[tid] = (float)sin(ang);
        }
        __syncthreads();
        for (int idx = tid; idx < 729; idx += 128) {
            {   // grid bases: idx = a*81 + s*9 + t
                int a = idx / 81, s = (idx / 9) % 9, t = idx % 9;
                Gx[idx] = gridval(Uxr, Uxi, a, s, t, C9, S9);
                Gf[idx] = gridval(Ufr, Ufi, a, s, t, C9, S9);
            }
            {   // projection: idx = (s*9+t)*9 + d
                int st = idx / 9, d = idx % 9;
                int s = st / 9, t = st % 9;
                float p = 0.0f;
                #pragma unroll
                for (int u = 0; u < 9; u++)
                    #pragma unroll
                    for (int k = 0; k < 5; k++) {
                        int th = (u * s + k * t) % 9;
                        p += Vr[u * 45 + k * 9 + d] * C9[th]
                           + Vi[u * 45 + k * 9 + d] * S9[th];
                    }
                Pm[idx] = p;
            }
        }
        __syncthreads();
        float inv = 1.0f / denom[0];
        for (int idx = tid; idx < 729; idx += 128) {
            int a = idx / 81, b = (idx / 9) % 9, d = idx % 9;
            float acc = 0.0f;
            #pragma unroll 9
            for (int st = 0; st < 81; st++)
                acc += Gx[a * 81 + st] * Gf[b * 81 + st] * Pm[st * 9 + d];
            g_T[(a * 9 + b) * 12 + d] = acc * inv;
        }
    } else {
        __syncthreads();   // match block-0 sync count? (not required across blocks;
        __syncthreads();   // keep per-block arrival uniform for the weight stage)
    }
    __syncthreads();       // w1s/w2s/w3s ready

    // ---- MLP for this block's edges ----
    int e = bid * 128 + tid;
    if (e >= E) return;

    const ulonglong2* w1p = (const ulonglong2*)w1s;
    const ulonglong2* w2p = (const ulonglong2*)w2s;
    const ulonglong2* w3p = (const ulonglong2*)w3s;

    float4 wa = ((const float4*)win)[e * 2 + 0];
    float4 wb = ((const float4*)win)[e * 2 + 1];
    float wi[8] = {wa.x, wa.y, wa.z, wa.w, wb.x, wb.y, wb.z, wb.w};

    u64 acc[32];
    float h[64];

    // layer 1
    #pragma unroll
    for (int t = 0; t < 32; t++) acc[t] = 0ull;
    #pragma unroll
    for (int i = 0; i < 8; i++) {
        u64 hi = pk2(wi[i], wi[i]);
        #pragma unroll
        for (int kq = 0; kq < 16; kq++) {
            ulonglong2 wp = w1p[i * 16 + kq];
            acc[2 * kq + 0] = ffma2(hi, wp.x, acc[2 * kq + 0]);
            acc[2 * kq + 1] = ffma2(hi, wp.y, acc[2 * kq + 1]);
        }
    }
    const float s1 = 0.35355339059327373f;
    #pragma unroll
    for (int t = 0; t < 32; t++) {
        float v0, v1; up2(acc[t], v0, v1);
        h[2 * t + 0] = sspf(v0 * s1);
        h[2 * t + 1] = sspf(v1 * s1);
    }

    // layer 2
    #pragma unroll
    for (int t = 0; t < 32; t++) acc[t] = 0ull;
    #pragma unroll 4
    for (int j = 0; j < 64; j++) {
        u64 hj = pk2(h[j], h[j]);
        #pragma unroll
        for (int kq = 0; kq < 16; kq++) {
            ulonglong2 wp = w2p[j * 16 + kq];
            acc[2 * kq + 0] = ffma2(hj, wp.x, acc[2 * kq + 0]);
            acc[2 * kq + 1] = ffma2(hj, wp.y, acc[2 * kq + 1]);
        }
    }
    #pragma unroll
    for (int t = 0; t < 32; t++) {
        float v0, v1; up2(acc[t], v0, v1);
        h[2 * t + 0] = sspf(v0 * 0.125f);
        h[2 * t + 1] = sspf(v1 * 0.125f);
    }

    // layer 3
    u64 acc3[24];
    #pragma unroll
    for (int t = 0; t < 24; t++) acc3[t] = 0ull;
    #pragma unroll 4
    for (int j = 0; j < 64; j++) {
        u64 hj = pk2(h[j], h[j]);
        #pragma unroll
        for (int q = 0; q < 12; q++) {
            ulonglong2 wp = w3p[j * 12 + q];
            acc3[2 * q + 0] = ffma2(hj, wp.x, acc3[2 * q + 0]);
            acc3[2 * q + 1] = ffma2(hj, wp.y, acc3[2 * q + 1]);
        }
    }
    float4* gwv = (float4*)&g_w[(size_t)e * 48];
    #pragma unroll
    for (int q = 0; q < 12; q++) {
        float p0, p1, p2, p3;
        up2(acc3[2 * q + 0], p0, p1);
        up2(acc3[2 * q + 1], p2, p3);
        gwv[q] = make_float4(p0 * 0.125f, p1 * 0.125f, p2 * 0.125f, p3 * 0.125f);
    }
}

// ---------------------------------------------------------------------------
// kmsg: warp-cooperative message + scatter. One warp owns 8 edges/iter.
//   stage:  x[src] rows -> smem (coalesced LDG.128, 9 rounds)
//   Sv:     edge's 4 lanes cooperatively build Sv[81] into smem (stride 81)
//   msg:    lane owns quarter qt of one edge (4 muls = 36 contiguous floats);
//           xf/rr in registers; 9 red.v4 per lane, 4-lane-contiguous (64B runs)
//   All sharing is intra-warp -> __syncwarp only.
// ---------------------------------------------------------------------------
#define KMSG_ITER 4   // 8-edge batches per warp

__global__ void __launch_bounds__(128) kmsg(const float* __restrict__ x,
                                            const float* __restrict__ fsph,
                                            const int*   __restrict__ eidx,
                                            const float* __restrict__ aw,
                                            float* __restrict__ out,
                                            int E) {
    __shared__ __align__(16) float Tsh[972];
    __shared__ float awsh[27];
    __shared__ __align__(16) float4 xsh[4][8 * 37];   // row stride 37 float4
    __shared__ float Svsh[4][8 * 81];

    int tid  = threadIdx.x;
    int wid  = tid >> 5;
    int lane = tid & 31;

    for (int i = tid; i < 972; i += 128) Tsh[i] = g_T[i];
    if (tid < 27) awsh[tid] = aw[tid];
    __syncthreads();

    const float4* x4 = (const float4*)x;
    int wbase = (blockIdx.x * 4 + wid) * (8 * KMSG_ITER);

    int eb_o = lane >> 2;     // edge this lane computes for
    int qt   = lane & 3;      // quarter of the 144 outputs

    for (int it = 0; it < KMSG_ITER; it++) {
        int base = wbase + it * 8;

        // per-lane edge metadata (lanes 0..7 hold the batch)
        int src8 = 0, dst8 = 0, v8 = 0;
        if (lane < 8) {
            int e8 = base + lane;
            if (e8 < E) {
                dst8 = __ldg(&eidx[e8]);
                src8 = __ldg(&eidx[E + e8]);
                v8 = 1;
            }
        }

        __syncwarp();   // previous iteration's readers done with xsh/Svsh

        // ---- stage x rows: 288 float4 in 9 coalesced rounds ----
        #pragma unroll
        for (int r = 0; r < 9; r++) {
            int flat = r * 32 + lane;
            int eb = flat / 36;
            int q  = flat - eb * 36;
            int s  = __shfl_sync(0xffffffffu, src8, eb);
            int vv = __shfl_sync(0xffffffffu, v8, eb);
            if (vv) xsh[wid][eb * 37 + q] = __ldg(&x4[(size_t)s * 36 + q]);
        }

        // ---- Sv build: 4 lanes per edge, lane qt covers a = qt, qt+4, (8) ----
        int e = base + eb_o;
        int valid = __shfl_sync(0xffffffffu, v8, eb_o);
        if (valid) {
            float f9[9];
            #pragma unroll
            for (int b = 0; b < 9; b++) f9[b] = __ldg(&fsph[(size_t)e * 9 + b]);
            #pragma unroll
            for (int a = qt; a < 9; a += 4) {
                float s0x=0.f,s0y=0.f,s0z=0.f,s0w=0.f;
                float s1x=0.f,s1y=0.f,s1z=0.f,s1w=0.f,s2=0.f;
                #pragma unroll
                for (int b = 0; b < 9; b++) {
                    float fb = f9[b];
                    const float4* tp = (const float4*)&Tsh[(a * 9 + b) * 12];
                    float4 t0 = tp[0];
                    float4 t1 = tp[1];
                    float  t2 = Tsh[(a * 9 + b) * 12 + 8];
                    s0x += fb*t0.x; s0y += fb*t0.y; s0z += fb*t0.z; s0w += fb*t0.w;
                    s1x += fb*t1.x; s1y += fb*t1.y; s1z += fb*t1.z; s1w += fb*t1.w;
                    s2  += fb*t2;
                }
                float* sv = &Svsh[wid][eb_o * 81 + a * 9];
                sv[0]=s0x; sv[1]=s0y; sv[2]=s0z; sv[3]=s0w;
                sv[4]=s1x; sv[5]=s1y; sv[6]=s1z; sv[7]=s1w; sv[8]=s2;
            }
        }
        __syncwarp();

        // ---- message for this lane's quarter ----
        if (valid) {
            int dst = __shfl_sync(0xffffffffu, dst8, eb_o);

            float xf[36];
            #pragma unroll
            for (int j = 0; j < 9; j++) {
                float4 v = xsh[wid][eb_o * 37 + qt * 9 + j];
                xf[j*4+0]=v.x; xf[j*4+1]=v.y; xf[j*4+2]=v.z; xf[j*4+3]=v.w;
            }
            float wf[12];
            const float4* wq4 = (const float4*)(g_w + (size_t)e * 48 + qt * 12);
            #pragma unroll
            for (int j = 0; j < 3; j++) {
                float4 v = __ldg(&wq4[j]);
                wf[j*4+0]=v.x; wf[j*4+1]=v.y; wf[j*4+2]=v.z; wf[j*4+3]=v.w;
            }

            float rr[36];
            const float* svb = &Svsh[wid][eb_o * 81];
            #pragma unroll
            for (int d = 0; d < 9; d++) {
                float sv[9];
                #pragma unroll
                for (int a = 0; a < 9; a++) sv[a] = svb[a * 9 + d];
                float A0 = awsh[d], A1 = awsh[9 + d], A2 = awsh[18 + d];
                #pragma unroll
                for (int mm = 0; mm < 4; mm++) {
                    float s = 0.f;
                    #pragma unroll
                    for (int a = 0; a < 9; a++) s += xf[mm * 9 + a] * sv[a];
                    float fac = wf[mm*3+0]*A0 + wf[mm*3+1]*A1 + wf[mm*3+2]*A2;
                    rr[mm * 9 + d] = s * fac;
                }
            }
            float* ob = out + (size_t)dst * 144 + qt * 36;
            #pragma unroll
            for (int q = 0; q < 9; q++) {
                asm volatile("red.global.add.v4.f32 [%0], {%1, %2, %3, %4};"
                             :: "l"(ob + q * 4),
                                "f"(rr[q*4+0]), "f"(rr[q*4+1]),
                                "f"(rr[q*4+2]), "f"(rr[q*4+3])
                             : "memory");
            }
        }
    }
}

// ---------------------------------------------------------------------------
// kernel_launch
// inputs: 0:x 1:filter_sph 2:weight_in 3:edge_idx 4:Ux_re 5:Ux_im 6:Uf_re
//         7:Uf_im 8:Vout_re 9:Vout_im 10:W1 11:W2 12:W3 13:a_w 14:denominator
// ---------------------------------------------------------------------------
extern "C" void kernel_launch(void* const* d_in, const int* in_sizes, int n_in,
                              void* d_out, int out_size) {
    const float* x    = (const float*)d_in[0];
    const float* fsph = (const float*)d_in[1];
    const float* win  = (const float*)d_in[2];
    const int*   eidx = (const int*)  d_in[3];
    const float* Uxr  = (const float*)d_in[4];
    const float* Uxi  = (const float*)d_in[5];
    const float* Ufr  = (const float*)d_in[6];
    const float* Ufi  = (const float*)d_in[7];
    const float* Vr   = (const float*)d_in[8];
    const float* Vi   = (const float*)d_in[9];
    const float* W1   = (const float*)d_in[10];
    const float* W2   = (const float*)d_in[11];
    const float* W3   = (const float*)d_in[12];
    const float* aw   = (const float*)d_in[13];
    const float* den  = (const float*)d_in[14];
    float* out = (float*)d_out;

    int E = in_sizes[1] / 9;   // filter_sph is [E, 9]
    int n4 = out_size / 4;

    int nb = (E + 127) / 128;
    kpre<<<nb, 128>>>(win, W1, W2, W3, Uxr, Uxi, Ufr, Ufi, Vr, Vi, den,
                      (float4*)out, n4, E);

    int epb = 4 * 8 * KMSG_ITER;   // edges per block
    kmsg<<<(E + epb - 1) / epb, 128>>>(x, fsph, eidx, aw, out, E);
}

// round 7
// speedup vs baseline: 1.6130x; 1.2204x over previous
#include <cuda_runtime.h>

// Problem constants (fixed shapes for this problem)
#define NNODE 10000
#define NEDGE 160000
#define NMUL  16

// Scratch (static device arrays — cudaMalloc is forbidden)
__device__ __align__(16) float g_T[972];                  // T[(a*9+b)*12 + d]
__device__ __align__(16) float g_w[(size_t)NEDGE * 48];   // transposed: float4 [12][E]
__device__ __align__(16) float g_f[(size_t)NEDGE * 9];    // transposed: [b][E]

typedef unsigned long long u64;

// ---------------------------------------------------------------------------
// packed f32x2 helpers (Blackwell FFMA2)
// ---------------------------------------------------------------------------
__device__ __forceinline__ u64 pk2(float x, float y) {
    u64 r; asm("mov.b64 %0, {%1, %2};" : "=l"(r) : "f"(x), "f"(y)); return r;
}
__device__ __forceinline__ void up2(u64 v, float& x, float& y) {
    asm("mov.b64 {%0, %1}, %2;" : "=f"(x), "=f"(y) : "l"(v));
}
__device__ __forceinline__ u64 ffma2(u64 a, u64 b, u64 c) {
    u64 d; asm("fma.rn.f32x2 %0, %1, %2, %3;" : "=l"(d) : "l"(a), "l"(b), "l"(c));
    return d;
}

__device__ __forceinline__ float sspf(float x) {
    float e = __expf(-fabsf(x));
    return fmaxf(x, 0.0f) + __logf(1.0f + e) - 0.69314718055994531f;
}

// ---------------------------------------------------------------------------
// gridval: real 9x9 grid value of one spherical basis vector through
// pad -> ifftshift -> truncate -> irfft2 (numpy Im(DC)-dropped convention)
// ---------------------------------------------------------------------------
__device__ __forceinline__ float gridval(const float* __restrict__ Ur,
                                         const float* __restrict__ Ui,
                                         int a, int s, int t,
                                         const float* C, const float* S) {
    float acc = 0.0f;
    #pragma unroll
    for (int v = 0; v < 5; v++) {
        float gr = 0.0f, gi = 0.0f;
        int jj = (v + 4) % 9 - 2;                 // padded col -> U col
        if (jj >= 0 && jj < 5) {
            #pragma unroll
            for (int u = 0; u < 9; u++) {
                int ii = (u + 4) % 9 - 2;         // padded row -> U row
                if (ii >= 0 && ii < 5) {
                    float cr = Ur[a * 25 + ii * 5 + jj];
                    float ci = Ui[a * 25 + ii * 5 + jj];
                    int k = (u * s) % 9;
                    gr += cr * C[k] - ci * S[k];
                    gi += cr * S[k] + ci * C[k];
                }
            }
        }
        if (v == 0) {
            acc += gr;                             // Im(DC) dropped
        } else {
            int k2 = (v * t) % 9;
            acc += 2.0f * (gr * C[k2] - gi * S[k2]);
        }
    }
    return acc * (1.0f / 81.0f);
}

// ---------------------------------------------------------------------------
// kpre: fused (a) zero out, (b) fsph transpose, (c) kprep (block 0),
// (d) per-edge 3-layer MLP 8->64->64->48 in packed FFMA2.
// ---------------------------------------------------------------------------
__global__ void __launch_bounds__(128) kpre(
    const float* __restrict__ win,
    const float* __restrict__ fsph,
    const float* __restrict__ W1,
    const float* __restrict__ W2,
    const float* __restrict__ W3,
    const float* __restrict__ Uxr, const float* __restrict__ Uxi,
    const float* __restrict__ Ufr, const float* __restrict__ Ufi,
    const float* __restrict__ Vr,  const float* __restrict__ Vi,
    const float* __restrict__ denom,
    float4* __restrict__ o4, int n4,
    int E) {
    __shared__ float4 w1s[128];   // 8x64
    __shared__ float4 w2s[1024];  // 64x64
    __shared__ float4 w3s[768];   // 64x48
    __shared__ float C9[9], S9[9];
    __shared__ float Gx[729], Gf[729], Pm[729];

    int tid = threadIdx.x;
    int bid = blockIdx.x;

    // ---- zero output (grid-stride) ----
    for (int i = bid * 128 + tid; i < n4; i += gridDim.x * 128)
        o4[i] = make_float4(0.f, 0.f, 0.f, 0.f);

    int e = bid * 128 + tid;

    // ---- fsph transpose: g_f[b][e] ----
    if (e < E) {
        #pragma unroll
        for (int b = 0; b < 9; b++)
            g_f[(size_t)b * E + e] = __ldg(&fsph[(size_t)e * 9 + b]);
    }

    // ---- stage MLP weights ----
    const float4* W1v = (const float4*)W1;
    const float4* W2v = (const float4*)W2;
    const float4* W3v = (const float4*)W3;
    w1s[tid] = W1v[tid];
    #pragma unroll
    for (int i = 0; i < 8; i++) w2s[tid + i * 128] = W2v[tid + i * 128];
    #pragma unroll
    for (int i = 0; i < 6; i++) w3s[tid + i * 128] = W3v[tid + i * 128];

    // ---- kprep on block 0 only (uniform branch per block) ----
    if (bid == 0) {
        if (tid < 9) {
            double ang = 2.0 * 3.14159265358979323846 * (double)tid / 9.0;
            C9[tid] = (float)cos(ang);
            S9[tid] = (float)sin(ang);
        }
        __syncthreads();
        for (int idx = tid; idx < 729; idx += 128) {
            {   // grid bases: idx = a*81 + s*9 + t
                int a = idx / 81, s = (idx / 9) % 9, t = idx % 9;
                Gx[idx] = gridval(Uxr, Uxi, a, s, t, C9, S9);
                Gf[idx] = gridval(Ufr, Ufi, a, s, t, C9, S9);
            }
            {   // projection: idx = (s*9+t)*9 + d
                int st = idx / 9, d = idx % 9;
                int s = st / 9, t = st % 9;
                float p = 0.0f;
                #pragma unroll
                for (int u = 0; u < 9; u++)
                    #pragma unroll
                    for (int k = 0; k < 5; k++) {
                        int th = (u * s + k * t) % 9;
                        p += Vr[u * 45 + k * 9 + d] * C9[th]
                           + Vi[u * 45 + k * 9 + d] * S9[th];
                    }
                Pm[idx] = p;
            }
        }
        __syncthreads();
        float inv = 1.0f / denom[0];
        for (int idx = tid; idx < 729; idx += 128) {
            int a = idx / 81, b = (idx / 9) % 9, d = idx % 9;
            float acc = 0.0f;
            #pragma unroll 9
            for (int st = 0; st < 81; st++)
                acc += Gx[a * 81 + st] * Gf[b * 81 + st] * Pm[st * 9 + d];
            g_T[(a * 9 + b) * 12 + d] = acc * inv;
        }
    } else {
        __syncthreads();
        __syncthreads();
    }
    __syncthreads();       // w1s/w2s/w3s ready

    // ---- MLP for this block's edges ----
    if (e >= E) return;

    const ulonglong2* w1p = (const ulonglong2*)w1s;
    const ulonglong2* w2p = (const ulonglong2*)w2s;
    const ulonglong2* w3p = (const ulonglong2*)w3s;

    float4 wa = ((const float4*)win)[e * 2 + 0];
    float4 wb = ((const float4*)win)[e * 2 + 1];
    float wi[8] = {wa.x, wa.y, wa.z, wa.w, wb.x, wb.y, wb.z, wb.w};

    u64 acc[32];
    float h[64];

    // layer 1
    #pragma unroll
    for (int t = 0; t < 32; t++) acc[t] = 0ull;
    #pragma unroll
    for (int i = 0; i < 8; i++) {
        u64 hi = pk2(wi[i], wi[i]);
        #pragma unroll
        for (int kq = 0; kq < 16; kq++) {
            ulonglong2 wp = w1p[i * 16 + kq];
            acc[2 * kq + 0] = ffma2(hi, wp.x, acc[2 * kq + 0]);
            acc[2 * kq + 1] = ffma2(hi, wp.y, acc[2 * kq + 1]);
        }
    }
    const float s1 = 0.35355339059327373f;
    #pragma unroll
    for (int t = 0; t < 32; t++) {
        float v0, v1; up2(acc[t], v0, v1);
        h[2 * t + 0] = sspf(v0 * s1);
        h[2 * t + 1] = sspf(v1 * s1);
    }

    // layer 2
    #pragma unroll
    for (int t = 0; t < 32; t++) acc[t] = 0ull;
    #pragma unroll 4
    for (int j = 0; j < 64; j++) {
        u64 hj = pk2(h[j], h[j]);
        #pragma unroll
        for (int kq = 0; kq < 16; kq++) {
            ulonglong2 wp = w2p[j * 16 + kq];
            acc[2 * kq + 0] = ffma2(hj, wp.x, acc[2 * kq + 0]);
            acc[2 * kq + 1] = ffma2(hj, wp.y, acc[2 * kq + 1]);
        }
    }
    #pragma unroll
    for (int t = 0; t < 32; t++) {
        float v0, v1; up2(acc[t], v0, v1);
        h[2 * t + 0] = sspf(v0 * 0.125f);
        h[2 * t + 1] = sspf(v1 * 0.125f);
    }

    // layer 3
    u64 acc3[24];
    #pragma unroll
    for (int t = 0; t < 24; t++) acc3[t] = 0ull;
    #pragma unroll 4
    for (int j = 0; j < 64; j++) {
        u64 hj = pk2(h[j], h[j]);
        #pragma unroll
        for (int q = 0; q < 12; q++) {
            ulonglong2 wp = w3p[j * 12 + q];
            acc3[2 * q + 0] = ffma2(hj, wp.x, acc3[2 * q + 0]);
            acc3[2 * q + 1] = ffma2(hj, wp.y, acc3[2 * q + 1]);
        }
    }
    // transposed store: g_w as float4 [12][E], coalesced per q
    float4* gw = (float4*)g_w;
    #pragma unroll
    for (int q = 0; q < 12; q++) {
        float p0, p1, p2, p3;
        up2(acc3[2 * q + 0], p0, p1);
        up2(acc3[2 * q + 1], p2, p3);
        gw[(size_t)q * E + e] =
            make_float4(p0 * 0.125f, p1 * 0.125f, p2 * 0.125f, p3 * 0.125f);
    }
}

// ---------------------------------------------------------------------------
// kmsg: thread-per-edge with
//   - transposed w reads  (coalesced, [12][E] float4)
//   - transposed f reads  (coalesced, [9][E])
//   - cooperative atomic flush via per-warp smem buffer, row stride 36 floats
//     (144 B = 9x16 B -> every float4 access is 16B-aligned; stores are
//     bank-conflict-free, flush loads ~2-way). Warp re-issues the reds with
//     4 lanes contiguous per edge (64B runs).
// ---------------------------------------------------------------------------
__global__ void __launch_bounds__(128, 3) kmsg(const float* __restrict__ x,
                                               const int*   __restrict__ eidx,
                                               const float* __restrict__ aw,
                                               float* __restrict__ out,
                                               int E) {
    __shared__ __align__(16) float Tsh[972];
    __shared__ float awsh[27];
    __shared__ __align__(16) float fbuf[4][32 * 36];   // per-warp flush buffer

    int tid  = threadIdx.x;
    int wid  = tid >> 5;
    int lane = tid & 31;

    #pragma unroll
    for (int i = 0; i < 8; i++) {
        int idx = tid + i * 128;
        if (idx < 972) Tsh[idx] = g_T[idx];
    }
    if (tid < 27) awsh[tid] = aw[tid];
    __syncthreads();

    int e = blockIdx.x * 128 + tid;
    int valid = (e < E) ? 1 : 0;
    int dst = 0, src = 0;
    if (valid) {
        dst = __ldg(&eidx[e]);
        src = __ldg(&eidx[E + e]);
    }

    // f9 from transposed layout (coalesced)
    float f9[9];
    #pragma unroll
    for (int b = 0; b < 9; b++)
        f9[b] = valid ? __ldg(&g_f[(size_t)b * E + e]) : 0.0f;

    // Sv[a][d] = sum_b f9[b] * T[a,b,d]
    float Sv[81];
    #pragma unroll
    for (int a = 0; a < 9; a++) {
        float s0x = 0.f, s0y = 0.f, s0z = 0.f, s0w = 0.f;
        float s1x = 0.f, s1y = 0.f, s1z = 0.f, s1w = 0.f;
        float s2 = 0.f;
        #pragma unroll
        for (int b = 0; b < 9; b++) {
            float fb = f9[b];
            const float4* tp = (const float4*)&Tsh[(a * 9 + b) * 12];
            float4 t0 = tp[0];
            float4 t1 = tp[1];
            float  t2 = Tsh[(a * 9 + b) * 12 + 8];
            s0x += fb * t0.x; s0y += fb * t0.y; s0z += fb * t0.z; s0w += fb * t0.w;
            s1x += fb * t1.x; s1y += fb * t1.y; s1z += fb * t1.z; s1w += fb * t1.w;
            s2  += fb * t2;
        }
        Sv[a * 9 + 0] = s0x; Sv[a * 9 + 1] = s0y; Sv[a * 9 + 2] = s0z; Sv[a * 9 + 3] = s0w;
        Sv[a * 9 + 4] = s1x; Sv[a * 9 + 5] = s1y; Sv[a * 9 + 6] = s1z; Sv[a * 9 + 7] = s1w;
        Sv[a * 9 + 8] = s2;
    }

    const float4* xq4 = (const float4*)(x + (size_t)src * 144);
    const float4* gw  = (const float4*)g_w;
    float4* fb = (float4*)&fbuf[wid][lane * 36];

    // 4 chunks of 4 muls; each chunk = 36 floats
    #pragma unroll 1
    for (int c = 0; c < 4; c++) {
        float xf[36];
        float wf[12];
        if (valid) {
            #pragma unroll
            for (int q = 0; q < 9; q++) {
                float4 v = __ldg(&xq4[c * 9 + q]);
                xf[q * 4 + 0] = v.x; xf[q * 4 + 1] = v.y;
                xf[q * 4 + 2] = v.z; xf[q * 4 + 3] = v.w;
            }
            #pragma unroll
            for (int q = 0; q < 3; q++) {
                float4 v = __ldg(&gw[(size_t)(c * 3 + q) * E + e]);
                wf[q * 4 + 0] = v.x; wf[q * 4 + 1] = v.y;
                wf[q * 4 + 2] = v.z; wf[q * 4 + 3] = v.w;
            }
        } else {
            #pragma unroll
            for (int q = 0; q < 36; q++) xf[q] = 0.f;
            #pragma unroll
            for (int q = 0; q < 12; q++) wf[q] = 0.f;
        }

        // compute and stage this chunk's 36 outputs
        #pragma unroll
        for (int q = 0; q < 9; q++) {
            float r[4];
            #pragma unroll
            for (int i = 0; i < 4; i++) {
                const int cf = q * 4 + i;
                const int mm = cf / 9;
                const int d  = cf % 9;
                float s = 0.f;
                #pragma unroll
                for (int a = 0; a < 9; a++) s += xf[mm * 9 + a] * Sv[a * 9 + d];
                float fac = wf[mm * 3 + 0] * awsh[d]
                          + wf[mm * 3 + 1] * awsh[9 + d]
                          + wf[mm * 3 + 2] * awsh[18 + d];
                r[i] = s * fac;
            }
            fb[q] = make_float4(r[0], r[1], r[2], r[3]);
        }
        __syncwarp();

        // cooperative flush: 4 groups of 8 edges; 4 lanes contiguous per edge
        #pragma unroll
        for (int g = 0; g < 4; g++) {
            int owner = 8 * g + (lane >> 2);
            int dste  = __shfl_sync(0xffffffffu, dst, owner);
            int ve    = __shfl_sync(0xffffffffu, valid, owner);
            const float4* sb = (const float4*)&fbuf[wid][owner * 36];
            float* ob = out + (size_t)dste * 144 + c * 36;
            #pragma unroll
            for (int r = 0; r < 2; r++) {
                int q = r * 4 + (lane & 3);
                float4 v = sb[q];
                if (ve)
                    asm volatile("red.global.add.v4.f32 [%0], {%1, %2, %3, %4};"
                                 :: "l"(ob + q * 4),
                                    "f"(v.x), "f"(v.y), "f"(v.z), "f"(v.w)
                                 : "memory");
            }
            if ((lane & 3) == 0) {
                float4 v = sb[8];
                if (ve)
                    asm volatile("red.global.add.v4.f32 [%0], {%1, %2, %3, %4};"
                                 :: "l"(ob + 32),
                                    "f"(v.x), "f"(v.y), "f"(v.z), "f"(v.w)
                                 : "memory");
            }
        }
        __syncwarp();
    }
}

// ---------------------------------------------------------------------------
// kernel_launch
// inputs: 0:x 1:filter_sph 2:weight_in 3:edge_idx 4:Ux_re 5:Ux_im 6:Uf_re
//         7:Uf_im 8:Vout_re 9:Vout_im 10:W1 11:W2 12:W3 13:a_w 14:denominator
// ---------------------------------------------------------------------------
extern "C" void kernel_launch(void* const* d_in, const int* in_sizes, int n_in,
                              void* d_out, int out_size) {
    const float* x    = (const float*)d_in[0];
    const float* fsph = (const float*)d_in[1];
    const float* win  = (const float*)d_in[2];
    const int*   eidx = (const int*)  d_in[3];
    const float* Uxr  = (const float*)d_in[4];
    const float* Uxi  = (const float*)d_in[5];
    const float* Ufr  = (const float*)d_in[6];
    const float* Ufi  = (const float*)d_in[7];
    const float* Vr   = (const float*)d_in[8];
    const float* Vi   = (const float*)d_in[9];
    const float* W1   = (const float*)d_in[10];
    const float* W2   = (const float*)d_in[11];
    const float* W3   = (const float*)d_in[12];
    const float* aw   = (const float*)d_in[13];
    const float* den  = (const float*)d_in[14];
    float* out = (float*)d_out;

    int E = in_sizes[1] / 9;   // filter_sph is [E, 9]
    int n4 = out_size / 4;

    int nb = (E + 127) / 128;
    kpre<<<nb, 128>>>(win, fsph, W1, W2, W3, Uxr, Uxi, Ufr, Ufi, Vr, Vi, den,
                      (float4*)out, n4, E);
    kmsg<<<nb, 128>>>(x, eidx, aw, out, E);
}